// round 2
// baseline (speedup 1.0000x reference)
#include <cuda_runtime.h>

// Problem constants (derived exactly from the reference's linspace/band math)
#define NB      32            // 8*4 flattened batches
#define CC      2             // channels summed into mag
#define FNUM    2999          // band freqs (30010..59990 step 10)
#define TNUM    400
#define FCIDX   1199          // band index of 42000 Hz
#define NNOISE  2598          // freqs with f<40000 (idx<999) or f>44000 (idx>=1400)
#define CH      64            // NB*CC leading channels of flattened x
#define FT      (FNUM*TNUM)   // 1,199,600
#define NSTRIDE (CC*FT)       // per-batch stride (2,399,200)
#define TOTAL   (CH*FT)       // 76,774,400 elements
#define TQ      (TNUM/4)      // 100 float4 per (f) row

#define SLICES  40            // noise-reduction slices per batch
#define FPS     65            // noise freqs per slice (40*65 >= 2598)
#define ZBLOCKS 1792          // zero-fill blocks
#define NOISEBLK (NB*SLICES)  // 1280 noise blocks

__device__ float d_partial[NB * SLICES];
__device__ int   d_mid[NB];
__device__ int   d_hb[NB];

// ---------------------------------------------------------------------------
// K1: fused zero-fill of output (write stream, streaming stores) +
//     per-(batch,slice) noise partial sums of sum_c |x| over noise freqs
//     (read stream, streaming loads). Both streams interleave across SMs.
// ---------------------------------------------------------------------------
__global__ __launch_bounds__(256) void k_zero_noise(const float* __restrict__ x,
                                                    float* __restrict__ out) {
    int b = blockIdx.x;
    if (b < ZBLOCKS) {
        const int nvec = TOTAL / 4;  // 19,193,600 float4 stores
        float4 z = make_float4(0.f, 0.f, 0.f, 0.f);
        float4* o4 = reinterpret_cast<float4*>(out);
        for (int i = b * 256 + threadIdx.x; i < nvec; i += ZBLOCKS * 256)
            __stcs(&o4[i], z);   // streaming: no reuse, keep out of L2
        return;
    }
    int nb = b - ZBLOCKS;
    int n  = nb / SLICES;
    int s  = nb % SLICES;
    int j0 = s * FPS;
    int j1 = min(NNOISE, j0 + FPS);
    int rows = (j1 - j0) * CC;     // (freqs in slice) x channels, <= 130
    const float4* base = reinterpret_cast<const float4*>(x) + (long long)n * (NSTRIDE / 4);

    // row-outer / quanta-inner: 256 threads = 2 full rows per pass (128 lanes
    // per row covers TQ=100 quanta), no integer division in the hot loop.
    int lane = threadIdx.x & 127;          // position within a row
    int half = threadIdx.x >> 7;           // 0 or 1: which row of the pair
    float acc = 0.f;
    for (int r = half; r < rows; r += 2) {
        int j = j0 + (r >> 1);             // noise-freq ordinal
        int c = r & 1;                     // channel
        int f = (j < 999) ? j : (j + 401); // ordinal -> band freq index
        const float4* rp = base + (long long)c * (FT / 4) + (long long)f * TQ;
        if (lane < TQ) {
            float4 v = __ldcs(&rp[lane]);  // streaming load
            acc += fabsf(v.x) + fabsf(v.y) + fabsf(v.z) + fabsf(v.w);
        }
    }
    __shared__ float sh[256];
    sh[threadIdx.x] = acc;
    __syncthreads();
    for (int st = 128; st > 0; st >>= 1) {
        if (threadIdx.x < st) sh[threadIdx.x] += sh[threadIdx.x + st];
        __syncthreads();
    }
    if (threadIdx.x == 0) d_partial[n * SLICES + s] = sh[0];
}

// ---------------------------------------------------------------------------
// K2: per-batch stats. mag row at FC_INDEX -> argmax (first-index-wins),
//     40-wide signal window sum, finalize noise mean, snr -> hb.
// ---------------------------------------------------------------------------
__global__ __launch_bounds__(256) void k_stats(const float* __restrict__ x) {
    int n = blockIdx.x;
    __shared__ float mag[TNUM];
    const float* p0 = x + (long long)n * NSTRIDE + (long long)FCIDX * TNUM;
    const float* p1 = p0 + FT;
    for (int t = threadIdx.x; t < TNUM; t += 256)
        mag[t] = fabsf(p0[t]) + fabsf(p1[t]);
    __syncthreads();
    if (threadIdx.x == 0) {
        // argmax: strictly-greater -> first index wins (jnp.argmax semantics)
        int mid = 0; float best = mag[0];
        for (int t = 1; t < TNUM; t++)
            if (mag[t] > best) { best = mag[t]; mid = t; }
        // sig = pulse[:, FC] : window [mid-20, mid+20) clipped to [0,T)
        float sig = 0.f;
        int lo = max(0, mid - 20), hi = min(TNUM, mid + 20);
        for (int t = lo; t < hi; t++) sig += mag[t];
        // noise mean over (noise freqs, T); channel sum is inside mag
        float noise = 0.f;
        for (int s = 0; s < SLICES; s++) noise += d_partial[n * SLICES + s];
        noise /= (float)(NNOISE * TNUM);
        // snr -> hb
        float d   = sig - noise;
        float snr = 10.0f * log10f((d * d) / (noise * noise));
        float hbf = truncf(6.0f * (snr - 48.0f) + 27.0f);
        hbf = fminf(hbf, 3000.0f);                 // clamp before int cast
        int hb = (hbf >= 8.0f) ? (int)hbf : 8;     // also maps NaN -> 8
        d_mid[n] = mid;
        d_hb[n]  = hb;
    }
}

// ---------------------------------------------------------------------------
// K3: scatter-copy kept rectangles. keep = union over n of
//     f in [FC-hb_n, FC+hb_n) x t in [mid_n-8, mid_n+8); each kept (f,t) is
//     copied for ALL 64 leading channels (keep broadcasts over batch+chan in
//     the reference). Overlapping rectangles write identical values ->
//     deterministic.
// ---------------------------------------------------------------------------
__global__ __launch_bounds__(256) void k_copy(const float* __restrict__ x,
                                              float* __restrict__ out) {
    int n   = blockIdx.y;
    int mid = d_mid[n];
    int hb  = d_hb[n];
    int flo = max(0, FCIDX - hb), fhi = min(FNUM, FCIDX + hb);
    int tlo = max(0, mid - 8),    thi = min(TNUM, mid + 8);
    int fw = fhi - flo, tw = thi - tlo;
    if (fw <= 0 || tw <= 0) return;
    long long cells = (long long)fw * tw;
    long long total = cells * CH;
    long long stride = (long long)gridDim.x * 256;
    for (long long i = (long long)blockIdx.x * 256 + threadIdx.x; i < total; i += stride) {
        long long ch   = i / cells;
        long long cell = i - ch * cells;
        int df = (int)(cell / tw);
        int f  = flo + df;
        int t  = tlo + (int)(cell - (long long)df * tw);
        long long off = ch * FT + (long long)f * TNUM + t;
        out[off] = x[off];
    }
}

extern "C" void kernel_launch(void* const* d_in, const int* in_sizes, int n_in,
                              void* d_out, int out_size) {
    const float* x = (const float*)d_in[0];
    float* out = (float*)d_out;
    (void)in_sizes; (void)n_in; (void)out_size;

    k_zero_noise<<<ZBLOCKS + NOISEBLK, 256>>>(x, out);
    k_stats<<<NB, 256>>>(x);
    k_copy<<<dim3(64, NB), 256>>>(x, out);
}

// round 4
// speedup vs baseline: 1.0796x; 1.0796x over previous
#include <cuda_runtime.h>

// Problem constants (derived exactly from the reference's linspace/band math)
#define NB      32            // 8*4 flattened batches
#define CC      2             // channels summed into mag
#define FNUM    2999          // band freqs (30010..59990 step 10)
#define TNUM    400
#define FCIDX   1199          // band index of 42000 Hz
#define NNOISE  2598          // freqs: idx<999 (f<40k) or idx>=1400 (f>44k)
#define CH      64            // NB*CC leading channels of flattened x
#define FT      (FNUM*TNUM)   // 1,199,600
#define NSTRIDE (CC*FT)       // per-batch stride (2,399,200)
#define TOTAL   (CH*FT)       // 76,774,400 elements

// float4-quanta geometry of the noise region (two contiguous chunks)
#define QA      99900         // chunk A: f in [0,999)     -> 999*100 quanta
#define QB      159900        // chunk B: f in [1400,2999) -> 1599*100 quanta
#define QC      (QA+QB)       // per (batch,channel): 259,800
#define QPB     (2*QC)        // per batch (both channels): 519,600
#define FT4     (FT/4)        // 299,900
#define BSTART  140000        // chunk B start offset in quanta (1400*100)

#define NOISEBX 64            // noise blocks per batch
#define ZBLOCKS 2048          // zero-fill blocks

__device__ float d_partial[NB * NOISEBX];
__device__ int   d_mid[NB];
__device__ int   d_hb[NB];

// ---------------------------------------------------------------------------
// K_noise: PURE-READ. Per-batch noise sum of sum_c |x| over the two
//          contiguous noise chunks, flat float4 grid-stride (full lanes,
//          perfectly coalesced). Unroll-4 front-batches independent LDG.128s
//          for MLP. One partial per (batch, block).
// ---------------------------------------------------------------------------
__global__ __launch_bounds__(256) void k_noise(const float* __restrict__ x) {
    int n = blockIdx.y;
    const float4* base = reinterpret_cast<const float4*>(x)
                       + (long long)n * (NSTRIDE / 4);
    float acc = 0.f;
    #pragma unroll 4
    for (int r = blockIdx.x * 256 + threadIdx.x; r < QPB; r += NOISEBX * 256) {
        int c  = (r >= QC) ? 1 : 0;
        int r2 = r - c * QC;
        // within-channel: A chunk maps 1:1; B chunk shifts by the gap
        int off = c * FT4 + ((r2 < QA) ? r2 : (r2 + (BSTART - QA)));
        float4 v = __ldcs(base + off);     // streaming: no reuse
        acc += fabsf(v.x) + fabsf(v.y) + fabsf(v.z) + fabsf(v.w);
    }
    __shared__ float sh[256];
    sh[threadIdx.x] = acc;
    __syncthreads();
    for (int st = 128; st > 0; st >>= 1) {
        if (threadIdx.x < st) sh[threadIdx.x] += sh[threadIdx.x + st];
        __syncthreads();
    }
    if (threadIdx.x == 0) d_partial[n * NOISEBX + blockIdx.x] = sh[0];
}

// ---------------------------------------------------------------------------
// K_zero: PURE-WRITE. Vectorized streaming zero-fill of the whole output.
// ---------------------------------------------------------------------------
__global__ __launch_bounds__(256) void k_zero(float* __restrict__ out) {
    const int nvec = TOTAL / 4;  // 19,193,600 float4 stores
    float4 z = make_float4(0.f, 0.f, 0.f, 0.f);
    float4* o4 = reinterpret_cast<float4*>(out);
    #pragma unroll 4
    for (int i = blockIdx.x * 256 + threadIdx.x; i < nvec; i += ZBLOCKS * 256)
        __stcs(&o4[i], z);
}

// ---------------------------------------------------------------------------
// K_stats: per-batch. mag row at FC_INDEX -> argmax (first-index-wins),
//          40-wide signal window sum, finalize noise mean, snr -> hb.
// ---------------------------------------------------------------------------
__global__ __launch_bounds__(256) void k_stats(const float* __restrict__ x) {
    int n = blockIdx.x;
    __shared__ float mag[TNUM];
    const float* p0 = x + (long long)n * NSTRIDE + (long long)FCIDX * TNUM;
    const float* p1 = p0 + FT;
    for (int t = threadIdx.x; t < TNUM; t += 256)
        mag[t] = fabsf(p0[t]) + fabsf(p1[t]);
    __syncthreads();
    if (threadIdx.x == 0) {
        // argmax: strictly-greater -> first index wins (jnp.argmax semantics)
        int mid = 0; float best = mag[0];
        for (int t = 1; t < TNUM; t++)
            if (mag[t] > best) { best = mag[t]; mid = t; }
        // sig = pulse[:, FC] : window [mid-20, mid+20) clipped to [0,T)
        float sig = 0.f;
        int lo = max(0, mid - 20), hi = min(TNUM, mid + 20);
        for (int t = lo; t < hi; t++) sig += mag[t];
        // noise mean over (noise freqs, T); channel sum lives inside mag
        float noise = 0.f;
        for (int s = 0; s < NOISEBX; s++) noise += d_partial[n * NOISEBX + s];
        noise /= (float)(NNOISE * TNUM);
        // snr -> hb
        float d   = sig - noise;
        float snr = 10.0f * log10f((d * d) / (noise * noise));
        float hbf = truncf(6.0f * (snr - 48.0f) + 27.0f);
        hbf = fminf(hbf, 3000.0f);                 // clamp before int cast
        int hb = (hbf >= 8.0f) ? (int)hbf : 8;     // also maps NaN -> 8
        d_mid[n] = mid;
        d_hb[n]  = hb;
    }
}

// ---------------------------------------------------------------------------
// K_copy: scatter-copy kept rectangles. keep = union over n of
//         f in [FC-hb_n, FC+hb_n) x t in [mid_n-8, mid_n+8); each kept (f,t)
//         is copied for ALL 64 leading channels (keep broadcasts over
//         batch+channel in the reference). Overlaps write identical values
//         -> deterministic.
// ---------------------------------------------------------------------------
__global__ __launch_bounds__(256) void k_copy(const float* __restrict__ x,
                                              float* __restrict__ out) {
    int n   = blockIdx.y;
    int mid = d_mid[n];
    int hb  = d_hb[n];
    int flo = max(0, FCIDX - hb), fhi = min(FNUM, FCIDX + hb);
    int tlo = max(0, mid - 8),    thi = min(TNUM, mid + 8);
    int fw = fhi - flo, tw = thi - tlo;
    if (fw <= 0 || tw <= 0) return;
    long long cells = (long long)fw * tw;
    long long total = cells * CH;
    long long stride = (long long)gridDim.x * 256;
    for (long long i = (long long)blockIdx.x * 256 + threadIdx.x; i < total; i += stride) {
        long long ch   = i / cells;
        long long cell = i - ch * cells;
        int df = (int)(cell / tw);
        int f  = flo + df;
        int t  = tlo + (int)(cell - (long long)df * tw);
        long long off = ch * FT + (long long)f * TNUM + t;
        out[off] = x[off];
    }
}

extern "C" void kernel_launch(void* const* d_in, const int* in_sizes, int n_in,
                              void* d_out, int out_size) {
    const float* x = (const float*)d_in[0];
    float* out = (float*)d_out;
    (void)in_sizes; (void)n_in; (void)out_size;

    k_noise<<<dim3(NOISEBX, NB), 256>>>(x);   // pure read  (266 MB)
    k_stats<<<NB, 256>>>(x);                  // tiny
    k_zero <<<ZBLOCKS, 256>>>(out);           // pure write (307 MB)
    k_copy <<<dim3(64, NB), 256>>>(x, out);   // tiny gather
}

// round 11
// speedup vs baseline: 1.1208x; 1.0382x over previous
#include <cuda_runtime.h>

// Problem constants (derived exactly from the reference's linspace/band math)
#define NB      32            // 8*4 flattened batches
#define CC      2             // channels summed into mag
#define FNUM    2999          // band freqs (30010..59990 step 10)
#define TNUM    400
#define FCIDX   1199          // band index of 42000 Hz
#define NNOISE  2598          // freqs: idx<999 (f<40k) or idx>=1400 (f>44k)
#define CH      64            // NB*CC leading channels of flattened x
#define FT      (FNUM*TNUM)   // 1,199,600
#define NSTRIDE (CC*FT)       // per-batch stride (2,399,200)
#define TOTAL   (CH*FT)       // 76,774,400 elements
#define TQ      (TNUM/4)      // 100 float4 per f-row

// float4-quanta geometry of the noise region (two contiguous chunks)
#define QA      99900         // chunk A: f in [0,999)     -> 999*100 quanta
#define QB      159900        // chunk B: f in [1400,2999) -> 1599*100 quanta
#define QC      (QA+QB)       // per (batch,channel): 259,800
#define QPB     (2*QC)        // per batch (both channels): 519,600
#define FT4     (FT/4)        // 299,900 quanta per channel
#define BSTART  140000        // chunk B start offset in quanta (1400*100)

#define NOISEBX 64            // noise blocks per batch
#define ZXBLK   32            // x-blocks for the fused zero+keep kernel

__device__ float d_partial[NB * NOISEBX];
__device__ int   d_mid[NB];
__device__ int   d_hb[NB];

// ---------------------------------------------------------------------------
// K_noise: PURE-READ. Per-batch noise sum of sum_c |x| over the two
//          contiguous noise chunks; flat float4 grid-stride, streaming loads.
// ---------------------------------------------------------------------------
__global__ __launch_bounds__(256) void k_noise(const float* __restrict__ x) {
    int n = blockIdx.y;
    const float4* base = reinterpret_cast<const float4*>(x)
                       + (long long)n * (NSTRIDE / 4);
    float acc = 0.f;
    #pragma unroll 4
    for (int r = blockIdx.x * 256 + threadIdx.x; r < QPB; r += NOISEBX * 256) {
        int c  = (r >= QC) ? 1 : 0;
        int r2 = r - c * QC;
        int off = c * FT4 + ((r2 < QA) ? r2 : (r2 + (BSTART - QA)));
        float4 v = __ldcs(base + off);
        acc += fabsf(v.x) + fabsf(v.y) + fabsf(v.z) + fabsf(v.w);
    }
    __shared__ float sh[256];
    sh[threadIdx.x] = acc;
    __syncthreads();
    for (int st = 128; st > 0; st >>= 1) {
        if (threadIdx.x < st) sh[threadIdx.x] += sh[threadIdx.x + st];
        __syncthreads();
    }
    if (threadIdx.x == 0) d_partial[n * NOISEBX + blockIdx.x] = sh[0];
}

// ---------------------------------------------------------------------------
// K_stats: per-batch. Parallel argmax (first-index-wins), 40-wide signal
//          window sum, noise mean finalize, snr -> hb.
// ---------------------------------------------------------------------------
__global__ __launch_bounds__(256) void k_stats(const float* __restrict__ x) {
    int n = blockIdx.x;
    __shared__ float mag[TNUM];
    __shared__ float bv[256];
    __shared__ int   bi[256];
    const float* p0 = x + (long long)n * NSTRIDE + (long long)FCIDX * TNUM;
    const float* p1 = p0 + FT;
    for (int t = threadIdx.x; t < TNUM; t += 256)
        mag[t] = fabsf(p0[t]) + fabsf(p1[t]);
    __syncthreads();
    // parallel argmax: strictly-greater wins; on exact tie, lower index wins
    float best = -1.f; int bidx = TNUM;
    for (int t = threadIdx.x; t < TNUM; t += 256)
        if (mag[t] > best) { best = mag[t]; bidx = t; }
    bv[threadIdx.x] = best; bi[threadIdx.x] = bidx;
    __syncthreads();
    for (int st = 128; st > 0; st >>= 1) {
        if (threadIdx.x < st) {
            float ov = bv[threadIdx.x + st]; int oi = bi[threadIdx.x + st];
            if (ov > bv[threadIdx.x] ||
                (ov == bv[threadIdx.x] && oi < bi[threadIdx.x])) {
                bv[threadIdx.x] = ov; bi[threadIdx.x] = oi;
            }
        }
        __syncthreads();
    }
    if (threadIdx.x == 0) {
        int mid = bi[0];
        float sig = 0.f;
        int lo = max(0, mid - 20), hi = min(TNUM, mid + 20);
        for (int t = lo; t < hi; t++) sig += mag[t];
        float noise = 0.f;
        for (int s = 0; s < NOISEBX; s++) noise += d_partial[n * NOISEBX + s];
        noise /= (float)(NNOISE * TNUM);
        float d   = sig - noise;
        float snr = 10.0f * log10f((d * d) / (noise * noise));
        float hbf = truncf(6.0f * (snr - 48.0f) + 27.0f);
        hbf = fminf(hbf, 3000.0f);
        int hb = (hbf >= 8.0f) ? (int)hbf : 8;   // also maps NaN -> 8
        d_mid[n] = mid;
        d_hb[n]  = hb;
    }
}

// ---------------------------------------------------------------------------
// K_zerokeep: PURE-WRITE fused with the keep-select. Union of keep f-ranges
//   is contiguous: [FC - max_hb, FC + max_hb). Common path = one index
//   compare + streaming zero store (no divisions). In-band quanta decode
//   (f,t), run the 32-batch keep test, and select x vs 0 per lane.
//   Overlapping rectangles produce identical values -> deterministic.
// ---------------------------------------------------------------------------
__global__ __launch_bounds__(256) void k_zerokeep(const float* __restrict__ x,
                                                  float* __restrict__ out) {
    __shared__ int s_mid[NB], s_hb[NB], s_q[2];
    if (threadIdx.x < NB) {
        s_mid[threadIdx.x] = d_mid[threadIdx.x];
        s_hb[threadIdx.x]  = d_hb[threadIdx.x];
    }
    if (threadIdx.x == 0) {
        int mh = 8;
        #pragma unroll
        for (int n = 0; n < NB; n++) mh = max(mh, d_hb[n]);
        int fmin = max(0, FCIDX - mh), fmax = min(FNUM, FCIDX + mh);
        s_q[0] = fmin * TQ;  // qlo
        s_q[1] = fmax * TQ;  // qhi
    }
    __syncthreads();
    int qlo = s_q[0], qhi = s_q[1];

    int ch = blockIdx.y;
    const float4* xi = reinterpret_cast<const float4*>(x) + (long long)ch * FT4;
    float4*       oo = reinterpret_cast<float4*>(out)     + (long long)ch * FT4;
    float4 z = make_float4(0.f, 0.f, 0.f, 0.f);

    #pragma unroll 4
    for (int i = blockIdx.x * 256 + threadIdx.x; i < FT4; i += ZXBLK * 256) {
        if (i >= qlo && i < qhi) {
            // in-band: decode (f, t) and run the 32-batch keep-union test
            int f  = i / TQ;
            int t0 = (i - f * TQ) * 4;     // first of 4 t's in this quantum
            bool k0 = false, k1 = false, k2 = false, k3 = false;
            #pragma unroll
            for (int n = 0; n < NB; n++) {
                int hb = s_hb[n];
                if (f >= FCIDX - hb && f < FCIDX + hb) {
                    int tlo = s_mid[n] - 8, thi = s_mid[n] + 8;
                    k0 |= (t0     >= tlo) & (t0     < thi);
                    k1 |= (t0 + 1 >= tlo) & (t0 + 1 < thi);
                    k2 |= (t0 + 2 >= tlo) & (t0 + 2 < thi);
                    k3 |= (t0 + 3 >= tlo) & (t0 + 3 < thi);
                }
            }
            float4 v = xi[i];
            float4 r;
            r.x = k0 ? v.x : 0.f;
            r.y = k1 ? v.y : 0.f;
            r.z = k2 ? v.z : 0.f;
            r.w = k3 ? v.w : 0.f;
            oo[i] = r;
        } else {
            __stcs(&oo[i], z);             // streaming zero store
        }
    }
}

extern "C" void kernel_launch(void* const* d_in, const int* in_sizes, int n_in,
                              void* d_out, int out_size) {
    const float* x = (const float*)d_in[0];
    float* out = (float*)d_out;
    (void)in_sizes; (void)n_in; (void)out_size;

    k_noise   <<<dim3(NOISEBX, NB), 256>>>(x);    // pure read  (266 MB)
    k_stats   <<<NB, 256>>>(x);                   // tiny
    k_zerokeep<<<dim3(ZXBLK, CH), 256>>>(x, out); // pure write (307 MB) + select
}

// round 12
// speedup vs baseline: 1.1215x; 1.0006x over previous
#include <cuda_runtime.h>

// Problem constants (derived exactly from the reference's linspace/band math)
#define NB      32            // 8*4 flattened batches
#define CC      2             // channels summed into mag
#define FNUM    2999          // band freqs (30010..59990 step 10)
#define TNUM    400
#define FCIDX   1199          // band index of 42000 Hz
#define NNOISE  2598          // freqs: idx<999 (f<40k) or idx>=1400 (f>44k)
#define CH      64            // NB*CC leading channels of flattened x
#define FT      (FNUM*TNUM)   // 1,199,600
#define NSTRIDE (CC*FT)       // per-batch stride (2,399,200)
#define TOTAL   (CH*FT)       // 76,774,400 elements
#define TQ      (TNUM/4)      // 100 float4 per f-row

// float4-quanta geometry of the noise region (two contiguous chunks)
#define QA      99900         // chunk A: f in [0,999)     -> 999*100 quanta
#define QB      159900        // chunk B: f in [1400,2999) -> 1599*100 quanta
#define QC      (QA+QB)       // per (batch,channel): 259,800
#define QPB     (2*QC)        // per batch (both channels): 519,600
#define FT4     (FT/4)        // 299,900 quanta per channel
#define BSTART  140000        // chunk B start offset in quanta (1400*100)

#define NOISEBX 64            // noise blocks per batch
#define ZXBLK   32            // x-blocks for the fused zero+keep kernel

__device__ float d_partial[NB * NOISEBX];
__device__ int   d_mid[NB];
__device__ int   d_hb[NB];

// ---------------------------------------------------------------------------
// K_noise: PURE-READ. Per-batch noise sum of sum_c |x| over the two
//          contiguous noise chunks; flat float4 grid-stride, streaming loads.
//          unroll 8 + dual accumulators -> 8 front-batched LDG.128 per window
//          (MLP_eff up from 4), breaking the FADD dependency chain.
// ---------------------------------------------------------------------------
__global__ __launch_bounds__(256) void k_noise(const float* __restrict__ x) {
    int n = blockIdx.y;
    const float4* base = reinterpret_cast<const float4*>(x)
                       + (long long)n * (NSTRIDE / 4);
    float acc0 = 0.f, acc1 = 0.f;
    #pragma unroll 8
    for (int r = blockIdx.x * 256 + threadIdx.x; r < QPB; r += NOISEBX * 256) {
        int c  = (r >= QC) ? 1 : 0;
        int r2 = r - c * QC;
        int off = c * FT4 + ((r2 < QA) ? r2 : (r2 + (BSTART - QA)));
        float4 v = __ldcs(base + off);
        acc0 += fabsf(v.x) + fabsf(v.y);
        acc1 += fabsf(v.z) + fabsf(v.w);
    }
    __shared__ float sh[256];
    sh[threadIdx.x] = acc0 + acc1;
    __syncthreads();
    for (int st = 128; st > 0; st >>= 1) {
        if (threadIdx.x < st) sh[threadIdx.x] += sh[threadIdx.x + st];
        __syncthreads();
    }
    if (threadIdx.x == 0) d_partial[n * NOISEBX + blockIdx.x] = sh[0];
}

// ---------------------------------------------------------------------------
// K_stats: per-batch. Parallel argmax (first-index-wins), 40-wide signal
//          window sum, noise mean finalize, snr -> hb.
// ---------------------------------------------------------------------------
__global__ __launch_bounds__(256) void k_stats(const float* __restrict__ x) {
    int n = blockIdx.x;
    __shared__ float mag[TNUM];
    __shared__ float bv[256];
    __shared__ int   bi[256];
    const float* p0 = x + (long long)n * NSTRIDE + (long long)FCIDX * TNUM;
    const float* p1 = p0 + FT;
    for (int t = threadIdx.x; t < TNUM; t += 256)
        mag[t] = fabsf(p0[t]) + fabsf(p1[t]);
    __syncthreads();
    // parallel argmax: strictly-greater wins; on exact tie, lower index wins
    float best = -1.f; int bidx = TNUM;
    for (int t = threadIdx.x; t < TNUM; t += 256)
        if (mag[t] > best) { best = mag[t]; bidx = t; }
    bv[threadIdx.x] = best; bi[threadIdx.x] = bidx;
    __syncthreads();
    for (int st = 128; st > 0; st >>= 1) {
        if (threadIdx.x < st) {
            float ov = bv[threadIdx.x + st]; int oi = bi[threadIdx.x + st];
            if (ov > bv[threadIdx.x] ||
                (ov == bv[threadIdx.x] && oi < bi[threadIdx.x])) {
                bv[threadIdx.x] = ov; bi[threadIdx.x] = oi;
            }
        }
        __syncthreads();
    }
    if (threadIdx.x == 0) {
        int mid = bi[0];
        float sig = 0.f;
        int lo = max(0, mid - 20), hi = min(TNUM, mid + 20);
        for (int t = lo; t < hi; t++) sig += mag[t];
        float noise = 0.f;
        for (int s = 0; s < NOISEBX; s++) noise += d_partial[n * NOISEBX + s];
        noise /= (float)(NNOISE * TNUM);
        float d   = sig - noise;
        float snr = 10.0f * log10f((d * d) / (noise * noise));
        float hbf = truncf(6.0f * (snr - 48.0f) + 27.0f);
        hbf = fminf(hbf, 3000.0f);
        int hb = (hbf >= 8.0f) ? (int)hbf : 8;   // also maps NaN -> 8
        d_mid[n] = mid;
        d_hb[n]  = hb;
    }
}

// ---------------------------------------------------------------------------
// K_zerokeep: PURE-WRITE fused with the keep-select. Union of keep f-ranges
//   is contiguous: [FC - max_hb, FC + max_hb). Common path = one index
//   compare + streaming zero store (no divisions). In-band quanta decode
//   (f,t), run the 32-batch keep test, and select x vs 0 per lane.
//   Overlapping rectangles produce identical values -> deterministic.
//   (Unchanged this round so its ncu cost lands cleanly attributable.)
// ---------------------------------------------------------------------------
__global__ __launch_bounds__(256) void k_zerokeep(const float* __restrict__ x,
                                                  float* __restrict__ out) {
    __shared__ int s_mid[NB], s_hb[NB], s_q[2];
    if (threadIdx.x < NB) {
        s_mid[threadIdx.x] = d_mid[threadIdx.x];
        s_hb[threadIdx.x]  = d_hb[threadIdx.x];
    }
    if (threadIdx.x == 0) {
        int mh = 8;
        #pragma unroll
        for (int n = 0; n < NB; n++) mh = max(mh, d_hb[n]);
        int fmin = max(0, FCIDX - mh), fmax = min(FNUM, FCIDX + mh);
        s_q[0] = fmin * TQ;  // qlo
        s_q[1] = fmax * TQ;  // qhi
    }
    __syncthreads();
    int qlo = s_q[0], qhi = s_q[1];

    int ch = blockIdx.y;
    const float4* xi = reinterpret_cast<const float4*>(x) + (long long)ch * FT4;
    float4*       oo = reinterpret_cast<float4*>(out)     + (long long)ch * FT4;
    float4 z = make_float4(0.f, 0.f, 0.f, 0.f);

    #pragma unroll 4
    for (int i = blockIdx.x * 256 + threadIdx.x; i < FT4; i += ZXBLK * 256) {
        if (i >= qlo && i < qhi) {
            // in-band: decode (f, t) and run the 32-batch keep-union test
            int f  = i / TQ;
            int t0 = (i - f * TQ) * 4;     // first of 4 t's in this quantum
            bool k0 = false, k1 = false, k2 = false, k3 = false;
            #pragma unroll
            for (int n = 0; n < NB; n++) {
                int hb = s_hb[n];
                if (f >= FCIDX - hb && f < FCIDX + hb) {
                    int tlo = s_mid[n] - 8, thi = s_mid[n] + 8;
                    k0 |= (t0     >= tlo) & (t0     < thi);
                    k1 |= (t0 + 1 >= tlo) & (t0 + 1 < thi);
                    k2 |= (t0 + 2 >= tlo) & (t0 + 2 < thi);
                    k3 |= (t0 + 3 >= tlo) & (t0 + 3 < thi);
                }
            }
            float4 v = xi[i];
            float4 r;
            r.x = k0 ? v.x : 0.f;
            r.y = k1 ? v.y : 0.f;
            r.z = k2 ? v.z : 0.f;
            r.w = k3 ? v.w : 0.f;
            oo[i] = r;
        } else {
            __stcs(&oo[i], z);             // streaming zero store
        }
    }
}

extern "C" void kernel_launch(void* const* d_in, const int* in_sizes, int n_in,
                              void* d_out, int out_size) {
    const float* x = (const float*)d_in[0];
    float* out = (float*)d_out;
    (void)in_sizes; (void)n_in; (void)out_size;

    k_noise   <<<dim3(NOISEBX, NB), 256>>>(x);    // pure read  (266 MB)
    k_stats   <<<NB, 256>>>(x);                   // tiny
    k_zerokeep<<<dim3(ZXBLK, CH), 256>>>(x, out); // pure write (307 MB) + select
}